// round 3
// baseline (speedup 1.0000x reference)
#include <cuda_runtime.h>
#include <math.h>

#define FULL 0xFFFFFFFFu

static constexpr int B_     = 2;
static constexpr int LQ_    = 13294;
static constexpr int LEN_IN_= 13294;
static constexpr int DM_    = 256;
static constexpr int NH_    = 8;
static constexpr int DH_    = 32;
static constexpr int M_ROWS = B_ * LQ_;          // 26588

// Scratch (static device globals: allocation-free)
__device__ float g_value[B_ * LEN_IN_ * DM_];    // [b, pos, h, d]  (26 MB)
__device__ float g_proj [M_ROWS * 384];          // [bq, 0:256 off | 256:384 aw]
__device__ float g_mid  [M_ROWS * DM_];          // [bq, h, d]
__device__ float g_Wcat [256 * 384];
__device__ float g_bcat [384];

__constant__ float c_WH[4] = {100.f, 50.f, 25.f, 13.f};   // square levels: W == H

// ---------------------------------------------------------------------------
// Pack [W_off | W_attn] into one [256, 384] weight + bias so the two query
// projections run as a single GEMM.
// ---------------------------------------------------------------------------
__global__ void pack_weights(const float* __restrict__ Woff,  const float* __restrict__ boff,
                             const float* __restrict__ Wattn, const float* __restrict__ battn)
{
    int i = blockIdx.x * blockDim.x + threadIdx.x;
    if (i < 256 * 384) {
        int k = i / 384, c = i % 384;
        g_Wcat[i] = (c < 256) ? Woff[k * 256 + c] : Wattn[k * 128 + (c - 256)];
    }
    if (i < 384) g_bcat[i] = (i < 256) ? boff[i] : battn[i - 256];
}

// ---------------------------------------------------------------------------
// SIMT SGEMM: C[M,N] = A[M,K] @ W[K,N] + bias.  BM=BN=128, BK=8, 8x8 microtile.
// N must be a multiple of 128. K a multiple of 8. Row guard on M only.
// ---------------------------------------------------------------------------
__global__ __launch_bounds__(256, 2)
void sgemm_bias(const float* __restrict__ A, const float* __restrict__ W,
                const float* __restrict__ bias, float* __restrict__ C,
                int M, int N, int K)
{
    __shared__ float As[8][132];   // transposed A tile, padded
    __shared__ float Bs[8][128];

    const int tid = threadIdx.x;
    const int tx  = tid & 15;       // 0..15 -> 8 cols each
    const int ty  = tid >> 4;       // 0..15 -> 8 rows each
    const int row0 = blockIdx.y * 128;
    const int col0 = blockIdx.x * 128;

    float acc[8][8];
#pragma unroll
    for (int i = 0; i < 8; i++)
#pragma unroll
        for (int j = 0; j < 8; j++) acc[i][j] = 0.f;

    const int aRow = tid >> 1;           // 0..127
    const int aCol = (tid & 1) * 4;      // 0 or 4
    const int bRow = tid >> 5;           // 0..7
    const int bCol = (tid & 31) * 4;     // 0..124

    for (int k0 = 0; k0 < K; k0 += 8) {
        float4 a4 = make_float4(0.f, 0.f, 0.f, 0.f);
        int ar = row0 + aRow;
        if (ar < M) a4 = *(const float4*)(A + (size_t)ar * K + k0 + aCol);
        As[aCol + 0][aRow] = a4.x;
        As[aCol + 1][aRow] = a4.y;
        As[aCol + 2][aRow] = a4.z;
        As[aCol + 3][aRow] = a4.w;

        float4 b4 = *(const float4*)(W + (size_t)(k0 + bRow) * N + col0 + bCol);
        *(float4*)&Bs[bRow][bCol] = b4;
        __syncthreads();

#pragma unroll
        for (int k = 0; k < 8; k++) {
            float ar_[8], br_[8];
            *(float4*)&ar_[0] = *(const float4*)&As[k][ty * 8];
            *(float4*)&ar_[4] = *(const float4*)&As[k][ty * 8 + 4];
            *(float4*)&br_[0] = *(const float4*)&Bs[k][tx * 8];
            *(float4*)&br_[4] = *(const float4*)&Bs[k][tx * 8 + 4];
#pragma unroll
            for (int i = 0; i < 8; i++)
#pragma unroll
                for (int j = 0; j < 8; j++)
                    acc[i][j] += ar_[i] * br_[j];
        }
        __syncthreads();
    }

#pragma unroll
    for (int i = 0; i < 8; i++) {
        int r = row0 + ty * 8 + i;
        if (r >= M) continue;
#pragma unroll
        for (int j = 0; j < 8; j += 4) {
            int c = col0 + tx * 8 + j;
            float4 bb = *(const float4*)(bias + c);
            float4 o;
            o.x = acc[i][j + 0] + bb.x;
            o.y = acc[i][j + 1] + bb.y;
            o.z = acc[i][j + 2] + bb.z;
            o.w = acc[i][j + 3] + bb.w;
            *(float4*)(C + (size_t)r * N + c) = o;
        }
    }
}

// ---------------------------------------------------------------------------
// Deformable sampling. One warp per (b, q, h): warp softmax over the 16
// attention logits, per-lane channel (d = lane) bilinear gather-accumulate.
// Corner loads are 32 consecutive floats -> one coalesced 128B transaction.
// ---------------------------------------------------------------------------
__global__ __launch_bounds__(256)
void msda_sample(const float* __restrict__ refp,   // [B, LQ, 4, 2]
                 const float* __restrict__ proj,   // [M, 384]
                 const float* __restrict__ value,  // [B, LEN_IN, 8, 32]
                 float* __restrict__ mid)          // [M, 256]
{
    const int bq   = blockIdx.x;            // 0 .. M_ROWS-1
    const int h    = threadIdx.x >> 5;      // 0..7
    const int lane = threadIdx.x & 31;
    const int b    = bq / LQ_;

    // Offsets: 32 per head (lane i holds offset component i)
    const float offv = proj[bq * 384 + h * 32 + lane];

    // Softmax over 16 logits for this head
    float a = (lane < 16) ? proj[bq * 384 + 256 + h * 16 + lane] : -1e30f;
    float m = a;
#pragma unroll
    for (int o = 16; o; o >>= 1) m = fmaxf(m, __shfl_xor_sync(FULL, m, o));
    float e = (lane < 16) ? __expf(a - m) : 0.f;
    float s = e;
#pragma unroll
    for (int o = 16; o; o >>= 1) s += __shfl_xor_sync(FULL, s, o);
    const float w = e / s;   // lane lp (<16) holds softmax weight for point lp

    // Per-point sampling coordinates (duplicated on lanes 16..31 via lp = lane&15)
    const int lp  = lane & 15;
    const int lvl = lp >> 2;
    const float wh = c_WH[lvl];
    const float rx = refp[(bq * 4 + lvl) * 2 + 0];
    const float ry = refp[(bq * 4 + lvl) * 2 + 1];
    const float ox = __shfl_sync(FULL, offv, 2 * lp);
    const float oy = __shfl_sync(FULL, offv, 2 * lp + 1);
    // normalizer for level = [W, H] and x = loc.x*W - 0.5 => ref.x*W + off.x - 0.5
    const float x = rx * wh + ox - 0.5f;
    const float y = ry * wh + oy - 0.5f;

    const float* vbase = value + (size_t)b * LEN_IN_ * DM_ + h * DH_ + lane;

    float acc = 0.f;
    const int kHW[4] = {100, 50, 25, 13};
    const int kS [4] = {0, 10000, 12500, 13125};

#pragma unroll
    for (int L = 0; L < 4; L++) {
        const int Wl = kHW[L];          // square: H == W
        const int Sl = kS[L];
#pragma unroll
        for (int p = 0; p < 4; p++) {
            const int src = L * 4 + p;
            const float xl = __shfl_sync(FULL, x, src);
            const float yl = __shfl_sync(FULL, y, src);
            const float wl = __shfl_sync(FULL, w, src);

            const float fx0 = floorf(xl), fy0 = floorf(yl);
            const int   x0  = (int)fx0,   y0  = (int)fy0;
            const float tx_ = xl - fx0,   ty_ = yl - fy0;

            const float w00 = (1.f - tx_) * (1.f - ty_) * wl;
            const float w01 = tx_ * (1.f - ty_) * wl;
            const float w10 = (1.f - tx_) * ty_ * wl;
            const float w11 = tx_ * ty_ * wl;

            const bool vx0 = (x0 >= 0)     && (x0 < Wl);
            const bool vx1 = (x0 + 1 >= 0) && (x0 + 1 < Wl);
            const bool vy0 = (y0 >= 0)     && (y0 < Wl);
            const bool vy1 = (y0 + 1 >= 0) && (y0 + 1 < Wl);

            if (vy0) {
                const int rowp = Sl + y0 * Wl;
                if (vx0) acc += w00 * vbase[(rowp + x0) * DM_];
                if (vx1) acc += w01 * vbase[(rowp + x0 + 1) * DM_];
            }
            if (vy1) {
                const int rowp = Sl + (y0 + 1) * Wl;
                if (vx0) acc += w10 * vbase[(rowp + x0) * DM_];
                if (vx1) acc += w11 * vbase[(rowp + x0 + 1) * DM_];
            }
        }
    }

    mid[bq * DM_ + h * DH_ + lane] = acc;
}

// ---------------------------------------------------------------------------
extern "C" void kernel_launch(void* const* d_in, const int* in_sizes, int n_in,
                              void* d_out, int out_size)
{
    const float* query  = (const float*)d_in[0];
    const float* refp   = (const float*)d_in[1];
    const float* inflat = (const float*)d_in[2];
    // d_in[3], d_in[4]: spatial shapes / level starts -- compile-time constants
    const float* W_off  = (const float*)d_in[5];
    const float* b_off  = (const float*)d_in[6];
    const float* W_attn = (const float*)d_in[7];
    const float* b_attn = (const float*)d_in[8];
    const float* W_val  = (const float*)d_in[9];
    const float* b_val  = (const float*)d_in[10];
    const float* W_out  = (const float*)d_in[11];
    const float* b_out  = (const float*)d_in[12];
    float* out = (float*)d_out;

    float *p_value, *p_proj, *p_mid, *p_Wcat, *p_bcat;
    cudaGetSymbolAddress((void**)&p_value, g_value);
    cudaGetSymbolAddress((void**)&p_proj,  g_proj);
    cudaGetSymbolAddress((void**)&p_mid,   g_mid);
    cudaGetSymbolAddress((void**)&p_Wcat,  g_Wcat);
    cudaGetSymbolAddress((void**)&p_bcat,  g_bcat);

    const int mblocks = (M_ROWS + 127) / 128;   // 208

    pack_weights<<<(256 * 384 + 255) / 256, 256>>>(W_off, b_off, W_attn, b_attn);

    dim3 gV(2, mblocks);   // N = 256
    sgemm_bias<<<gV, 256>>>(inflat, W_val, b_val, p_value, M_ROWS, 256, 256);

    dim3 gP(3, mblocks);   // N = 384
    sgemm_bias<<<gP, 256>>>(query, p_Wcat, p_bcat, p_proj, M_ROWS, 384, 256);

    msda_sample<<<M_ROWS, 256>>>(refp, p_proj, p_value, p_mid);

    dim3 gO(2, mblocks);   // N = 256
    sgemm_bias<<<gO, 256>>>(p_mid, W_out, b_out, out, M_ROWS, 256, 256);
}

// round 5
// speedup vs baseline: 1.1868x; 1.1868x over previous
#include <cuda_runtime.h>
#include <math.h>

#define FULL 0xFFFFFFFFu

static constexpr int B_     = 2;
static constexpr int LQ_    = 13294;
static constexpr int LEN_IN_= 13294;
static constexpr int DM_    = 256;
static constexpr int M_ROWS = B_ * LQ_;          // 26588

// Scratch (static device globals: allocation-free)
__device__ float g_value[B_ * LEN_IN_ * DM_];    // [b, pos, h, d]  (26 MB)
__device__ float g_proj [M_ROWS * 384];          // [bq, 0:256 off | 256:384 aw]
__device__ float g_mid  [M_ROWS * DM_];          // [bq, h, d]
__device__ float g_Wcat [256 * 384];
__device__ float g_bcat [384];

__constant__ float c_WH[4] = {100.f, 50.f, 25.f, 13.f};   // square levels
__constant__ int   c_Wi[4] = {100, 50, 25, 13};
__constant__ int   c_S [4] = {0, 10000, 12500, 13125};

// ---------------------------------------------------------------------------
// f32x2 packed helpers (Blackwell FFMA2 path — only reachable via PTX)
// ---------------------------------------------------------------------------
__device__ __forceinline__ unsigned long long pack2(float x, float y) {
    unsigned long long r;
    asm("mov.b64 %0, {%1, %2};" : "=l"(r) : "f"(x), "f"(y));
    return r;
}
__device__ __forceinline__ void ffma2(unsigned long long& d,
                                      unsigned long long a, unsigned long long b) {
    asm("fma.rn.f32x2 %0, %1, %2, %3;" : "=l"(d) : "l"(a), "l"(b), "l"(d));
}
__device__ __forceinline__ void unpack2(unsigned long long v, float& lo, float& hi) {
    asm("mov.b64 {%0, %1}, %2;" : "=f"(lo), "=f"(hi) : "l"(v));
}

// ---------------------------------------------------------------------------
// Pack [W_off | W_attn] into one [256, 384] weight + bias.
// ---------------------------------------------------------------------------
__global__ void pack_weights(const float* __restrict__ Woff,  const float* __restrict__ boff,
                             const float* __restrict__ Wattn, const float* __restrict__ battn)
{
    int i = blockIdx.x * blockDim.x + threadIdx.x;
    if (i < 256 * 384) {
        int k = i / 384, c = i % 384;
        g_Wcat[i] = (c < 256) ? Woff[k * 256 + c] : Wattn[k * 128 + (c - 256)];
    }
    if (i < 384) g_bcat[i] = (i < 256) ? boff[i] : battn[i - 256];
}

// ---------------------------------------------------------------------------
// SGEMM with packed f32x2 FMAs. BM=BN=128, BK=8, 8x8 microtile (as 8x4 f32x2).
// ---------------------------------------------------------------------------
__global__ __launch_bounds__(256, 2)
void sgemm_bias(const float* __restrict__ A, const float* __restrict__ W,
                const float* __restrict__ bias, float* __restrict__ C,
                int M, int N, int K)
{
    __shared__ float As[8][132];   // transposed A tile, padded
    __shared__ float Bs[8][128];

    const int tid = threadIdx.x;
    const int tx  = tid & 15;
    const int ty  = tid >> 4;
    const int row0 = blockIdx.y * 128;
    const int col0 = blockIdx.x * 128;

    unsigned long long acc2[8][4];
#pragma unroll
    for (int i = 0; i < 8; i++)
#pragma unroll
        for (int j = 0; j < 4; j++) acc2[i][j] = 0ull;

    const int aRow = tid >> 1;
    const int aCol = (tid & 1) * 4;
    const int bRow = tid >> 5;
    const int bCol = (tid & 31) * 4;

    for (int k0 = 0; k0 < K; k0 += 8) {
        float4 a4 = make_float4(0.f, 0.f, 0.f, 0.f);
        int ar = row0 + aRow;
        if (ar < M) a4 = *(const float4*)(A + (size_t)ar * K + k0 + aCol);
        As[aCol + 0][aRow] = a4.x;
        As[aCol + 1][aRow] = a4.y;
        As[aCol + 2][aRow] = a4.z;
        As[aCol + 3][aRow] = a4.w;

        float4 b4 = *(const float4*)(W + (size_t)(k0 + bRow) * N + col0 + bCol);
        *(float4*)&Bs[bRow][bCol] = b4;
        __syncthreads();

#pragma unroll
        for (int k = 0; k < 8; k++) {
            float ar_[8], br_[8];
            *(float4*)&ar_[0] = *(const float4*)&As[k][ty * 8];
            *(float4*)&ar_[4] = *(const float4*)&As[k][ty * 8 + 4];
            *(float4*)&br_[0] = *(const float4*)&Bs[k][tx * 8];
            *(float4*)&br_[4] = *(const float4*)&Bs[k][tx * 8 + 4];

            unsigned long long ad[8], bd[4];
#pragma unroll
            for (int i = 0; i < 8; i++) ad[i] = pack2(ar_[i], ar_[i]);
#pragma unroll
            for (int j = 0; j < 4; j++) bd[j] = pack2(br_[2 * j], br_[2 * j + 1]);
#pragma unroll
            for (int i = 0; i < 8; i++)
#pragma unroll
                for (int j = 0; j < 4; j++)
                    ffma2(acc2[i][j], ad[i], bd[j]);
        }
        __syncthreads();
    }

#pragma unroll
    for (int i = 0; i < 8; i++) {
        int r = row0 + ty * 8 + i;
        if (r >= M) continue;
        float o_[8];
#pragma unroll
        for (int j = 0; j < 4; j++) unpack2(acc2[i][j], o_[2 * j], o_[2 * j + 1]);
#pragma unroll
        for (int j = 0; j < 8; j += 4) {
            int c = col0 + tx * 8 + j;
            float4 bb = *(const float4*)(bias + c);
            float4 o;
            o.x = o_[j + 0] + bb.x;
            o.y = o_[j + 1] + bb.y;
            o.z = o_[j + 2] + bb.z;
            o.w = o_[j + 3] + bb.w;
            *(float4*)(C + (size_t)r * N + c) = o;
        }
    }
}

// ---------------------------------------------------------------------------
// Deformable sampling, two phases per block (one block per bq):
//   Phase 1: 128 threads compute per-(head,point) softmax weight, bilinear
//            corner weights (validity-masked to 0), and 4 clamped element
//            offsets -> smem table.
//   Phase 2: warp h, lane = channel d: 16 points x (2 uniform LDS.128 +
//            4 LDG + 4 FFMA). No branches, no shuffles.
// ---------------------------------------------------------------------------
__global__ __launch_bounds__(256)
void msda_sample(const float* __restrict__ refp,   // [B, LQ, 4, 2]
                 const float* __restrict__ proj,   // [M, 384]
                 const float* __restrict__ value,  // [B, LEN_IN, 8, 32]
                 float* __restrict__ mid)          // [M, 256]
{
    __shared__ float4 sW[128];
    __shared__ int4   sO[128];

    const int bq = blockIdx.x;
    const int t  = threadIdx.x;
    const int b  = bq / LQ_;

    if (t < 128) {
        const int h   = t >> 4;
        const int p   = t & 15;
        const int lvl = p >> 2;
        const int pp  = p & 3;

        // softmax over 16 logits of this head (lanes form 16-groups in-warp)
        float a = proj[bq * 384 + 256 + h * 16 + p];
        float m = a;
#pragma unroll
        for (int o = 8; o; o >>= 1) m = fmaxf(m, __shfl_xor_sync(FULL, m, o));
        float e = __expf(a - m);
        float s = e;
#pragma unroll
        for (int o = 8; o; o >>= 1) s += __shfl_xor_sync(FULL, s, o);
        const float w = e / s;

        const float wh = c_WH[lvl];
        const int   Wl = c_Wi[lvl];
        const int   Sl = c_S[lvl];
        const float ox = proj[bq * 384 + h * 32 + lvl * 8 + pp * 2 + 0];
        const float oy = proj[bq * 384 + h * 32 + lvl * 8 + pp * 2 + 1];
        const float rx = refp[(bq * 4 + lvl) * 2 + 0];
        const float ry = refp[(bq * 4 + lvl) * 2 + 1];

        const float x = fmaf(rx, wh, ox) - 0.5f;
        const float y = fmaf(ry, wh, oy) - 0.5f;

        const float fx0 = floorf(x), fy0 = floorf(y);
        const int   x0  = (int)fx0,  y0  = (int)fy0;
        const float tx_ = x - fx0,   ty_ = y - fy0;

        const bool vx0 = (x0 >= 0)     && (x0 < Wl);
        const bool vx1 = (x0 + 1 >= 0) && (x0 + 1 < Wl);
        const bool vy0 = (y0 >= 0)     && (y0 < Wl);
        const bool vy1 = (y0 + 1 >= 0) && (y0 + 1 < Wl);

        const int cx0 = min(max(x0, 0),     Wl - 1);
        const int cx1 = min(max(x0 + 1, 0), Wl - 1);
        const int cy0 = min(max(y0, 0),     Wl - 1);
        const int cy1 = min(max(y0 + 1, 0), Wl - 1);

        float4 wv;
        wv.x = (vx0 && vy0) ? (1.f - tx_) * (1.f - ty_) * w : 0.f;
        wv.y = (vx1 && vy0) ? tx_ * (1.f - ty_) * w : 0.f;
        wv.z = (vx0 && vy1) ? (1.f - tx_) * ty_ * w : 0.f;
        wv.w = (vx1 && vy1) ? tx_ * ty_ * w : 0.f;

        const int base = b * LEN_IN_ * DM_ + h * 32;
        int4 ov;
        ov.x = base + (Sl + cy0 * Wl + cx0) * DM_;
        ov.y = base + (Sl + cy0 * Wl + cx1) * DM_;
        ov.z = base + (Sl + cy1 * Wl + cx0) * DM_;
        ov.w = base + (Sl + cy1 * Wl + cx1) * DM_;

        sW[t] = wv;
        sO[t] = ov;
    }
    __syncthreads();

    const int h    = t >> 5;
    const int lane = t & 31;
    const float* __restrict__ vp = value + lane;

    float acc = 0.f;
#pragma unroll
    for (int p = 0; p < 16; p++) {
        const float4 wv = sW[h * 16 + p];
        const int4   ov = sO[h * 16 + p];
        acc = fmaf(wv.x, __ldg(vp + ov.x), acc);
        acc = fmaf(wv.y, __ldg(vp + ov.y), acc);
        acc = fmaf(wv.z, __ldg(vp + ov.z), acc);
        acc = fmaf(wv.w, __ldg(vp + ov.w), acc);
    }

    mid[bq * DM_ + h * 32 + lane] = acc;
}

// ---------------------------------------------------------------------------
extern "C" void kernel_launch(void* const* d_in, const int* in_sizes, int n_in,
                              void* d_out, int out_size)
{
    const float* query  = (const float*)d_in[0];
    const float* refp   = (const float*)d_in[1];
    const float* inflat = (const float*)d_in[2];
    const float* W_off  = (const float*)d_in[5];
    const float* b_off  = (const float*)d_in[6];
    const float* W_attn = (const float*)d_in[7];
    const float* b_attn = (const float*)d_in[8];
    const float* W_val  = (const float*)d_in[9];
    const float* b_val  = (const float*)d_in[10];
    const float* W_out  = (const float*)d_in[11];
    const float* b_out  = (const float*)d_in[12];
    float* out = (float*)d_out;

    float *p_value, *p_proj, *p_mid, *p_Wcat, *p_bcat;
    cudaGetSymbolAddress((void**)&p_value, g_value);
    cudaGetSymbolAddress((void**)&p_proj,  g_proj);
    cudaGetSymbolAddress((void**)&p_mid,   g_mid);
    cudaGetSymbolAddress((void**)&p_Wcat,  g_Wcat);
    cudaGetSymbolAddress((void**)&p_bcat,  g_bcat);

    const int mblocks = (M_ROWS + 127) / 128;   // 208

    pack_weights<<<(256 * 384 + 255) / 256, 256>>>(W_off, b_off, W_attn, b_attn);

    dim3 gV(2, mblocks);   // N = 256
    sgemm_bias<<<gV, 256>>>(inflat, W_val, b_val, p_value, M_ROWS, 256, 256);

    dim3 gP(3, mblocks);   // N = 384
    sgemm_bias<<<gP, 256>>>(query, p_Wcat, p_bcat, p_proj, M_ROWS, 384, 256);

    msda_sample<<<M_ROWS, 256>>>(refp, p_proj, p_value, p_mid);

    dim3 gO(2, mblocks);   // N = 256
    sgemm_bias<<<gO, 256>>>(p_mid, W_out, b_out, out, M_ROWS, 256, 256);
}

// round 7
// speedup vs baseline: 1.8711x; 1.5766x over previous
#include <cuda_runtime.h>
#include <cuda_bf16.h>
#include <math.h>
#include <stdint.h>

#define FULL 0xFFFFFFFFu

static constexpr int B_      = 2;
static constexpr int LQ_     = 13294;
static constexpr int LEN_IN_ = 13294;
static constexpr int DM_     = 256;
static constexpr int M_ROWS  = B_ * LQ_;      // 26588
static constexpr int MT_     = 208;           // M tiles of 128
static constexpr int M_PAD   = MT_ * 128;     // 26624

// ---------------- scratch (static device globals; allocation-free) ----------
// A_cat layout: [M_PAD, 512] bf16 : cols 0..255 = hi(x), 256..511 = lo(x)
__device__ __align__(128) __nv_bfloat16 g_Acat1[M_PAD * 512];  // bf16(inflat)
__device__ __align__(128) __nv_bfloat16 g_Acat2[M_PAD * 512];  // bf16(query)
__device__ __align__(128) __nv_bfloat16 g_Acat3[M_PAD * 512];  // bf16(sampled mid)
// B_cat layout: [N, 512] bf16 : B[n,k] = W[k,n]; cols 0..255 hi, 256..511 lo
__device__ __align__(128) __nv_bfloat16 g_Bval[256 * 512];
__device__ __align__(128) __nv_bfloat16 g_Bqkv[384 * 512];
__device__ __align__(128) __nv_bfloat16 g_Bout[256 * 512];
__device__ float g_bcat[384];
__device__ float g_value[M_ROWS * 256];       // fp32 value (sampler input)
__device__ float g_proj [M_ROWS * 384];       // fp32 [off(256) | logits(128)]

__constant__ float c_WH[4] = {100.f, 50.f, 25.f, 13.f};
__constant__ int   c_Wi[4] = {100, 50, 25, 13};
__constant__ int   c_S [4] = {0, 10000, 12500, 13125};

// ---------------- helpers ---------------------------------------------------
__device__ __forceinline__ void split_bf16(float x, __nv_bfloat16& h, __nv_bfloat16& l) {
    h = __float2bfloat16(x);
    l = __float2bfloat16(x - __bfloat162float(h));
}
__device__ __forceinline__ uint32_t smem_u32(const void* p) {
    uint32_t a;
    asm("{ .reg .u64 t; cvta.to.shared.u64 t, %1; cvt.u32.u64 %0, t; }" : "=r"(a) : "l"(p));
    return a;
}
__device__ __forceinline__ void ldsm4(uint32_t* r, uint32_t a) {
    asm volatile("ldmatrix.sync.aligned.m8n8.x4.shared.b16 {%0,%1,%2,%3}, [%4];"
                 : "=r"(r[0]), "=r"(r[1]), "=r"(r[2]), "=r"(r[3]) : "r"(a));
}
__device__ __forceinline__ void mma16816(float* d, const uint32_t* a,
                                         uint32_t b0, uint32_t b1) {
    asm volatile(
        "mma.sync.aligned.m16n8k16.row.col.f32.bf16.bf16.f32 "
        "{%0,%1,%2,%3}, {%4,%5,%6,%7}, {%8,%9}, {%0,%1,%2,%3};"
        : "+f"(d[0]), "+f"(d[1]), "+f"(d[2]), "+f"(d[3])
        : "r"(a[0]), "r"(a[1]), "r"(a[2]), "r"(a[3]), "r"(b0), "r"(b1));
}

// ---------------------------------------------------------------------------
// Pack weights: B[n, 0:256]=bf16_hi(W[k,n]), B[n, 256:512]=bf16_lo. Plus the
// concatenated bias and zero-fill of the A_cat pad rows.
// ---------------------------------------------------------------------------
__global__ void pack_misc(const float* __restrict__ Woff,  const float* __restrict__ boff,
                          const float* __restrict__ Wattn, const float* __restrict__ battn,
                          const float* __restrict__ Wval,  const float* __restrict__ Wout)
{
    const int i = blockIdx.x * blockDim.x + threadIdx.x;
    const int which = blockIdx.y;
    if (which == 0) {
        if (i < 256 * 512) {
            int n = i >> 9, kk = i & 511, k = kk & 255;
            float w = Wval[k * 256 + n];
            __nv_bfloat16 h, l; split_bf16(w, h, l);
            g_Bval[i] = (kk < 256) ? h : l;
        }
    } else if (which == 1) {
        if (i < 384 * 512) {
            int n = i >> 9, kk = i & 511, k = kk & 255;
            float w = (n < 256) ? Woff[k * 256 + n] : Wattn[k * 128 + (n - 256)];
            __nv_bfloat16 h, l; split_bf16(w, h, l);
            g_Bqkv[i] = (kk < 256) ? h : l;
        }
    } else if (which == 2) {
        if (i < 256 * 512) {
            int n = i >> 9, kk = i & 511, k = kk & 255;
            float w = Wout[k * 256 + n];
            __nv_bfloat16 h, l; split_bf16(w, h, l);
            g_Bout[i] = (kk < 256) ? h : l;
        }
    } else {
        if (i < 384) g_bcat[i] = (i < 256) ? boff[i] : battn[i - 256];
        int j = i - 384;
        const int PADE = (M_PAD - M_ROWS) * 512;   // 36*512
        if (j >= 0 && j < 3 * PADE) {
            int arr = j / PADE, off = j % PADE;
            __nv_bfloat16 z = __float2bfloat16(0.f);
            __nv_bfloat16* dst = (arr == 0) ? g_Acat1 : (arr == 1) ? g_Acat2 : g_Acat3;
            dst[M_ROWS * 512 + off] = z;
        }
    }
}

// ---------------------------------------------------------------------------
// fp32 [M,256] -> bf16 split [M,512] for inflat (y=0) and query (y=1).
// ---------------------------------------------------------------------------
__global__ void convert_split(const float* __restrict__ inflat,
                              const float* __restrict__ query)
{
    const int e4 = blockIdx.x * blockDim.x + threadIdx.x;
    if (e4 >= M_ROWS * 64) return;
    const float* src = blockIdx.y ? query : inflat;
    __nv_bfloat16* dst = blockIdx.y ? g_Acat2 : g_Acat1;
    const int row = e4 >> 6;
    const int c4  = (e4 & 63) << 2;
    float4 v = *(const float4*)(src + (size_t)row * 256 + c4);
    __nv_bfloat16 h0, l0, h1, l1, h2, l2, h3, l3;
    split_bf16(v.x, h0, l0); split_bf16(v.y, h1, l1);
    split_bf16(v.z, h2, l2); split_bf16(v.w, h3, l3);
    __nv_bfloat162* dh = (__nv_bfloat162*)(dst + (size_t)row * 512 + c4);
    dh[0] = __halves2bfloat162(h0, h1);
    dh[1] = __halves2bfloat162(h2, h3);
    __nv_bfloat162* dl = (__nv_bfloat162*)(dst + (size_t)row * 512 + 256 + c4);
    dl[0] = __halves2bfloat162(l0, l1);
    dl[1] = __halves2bfloat162(l2, l3);
}

// ---------------------------------------------------------------------------
// bf16 split GEMM via warp-level mma.sync (HMMA). One CTA = 128x128 tile,
// 256 threads = 8 warps in a 2x4 (M x N) grid, warp tile 64x32.
// K loop: 12 chunks of 64 (3 segments: Ahi*Bhi, Alo*Bhi, Ahi*Blo), fp32 acc.
// SMEM: XOR-swizzled 128B rows, conflict-free ldmatrix.x4; double buffered
// with register-staged global loads.
// ---------------------------------------------------------------------------
__global__ __launch_bounds__(256, 1)
void gemm_bf16_mma(const __nv_bfloat16* __restrict__ A,   // [M_PAD, 512]
                   const __nv_bfloat16* __restrict__ Bm,  // [N, 512]
                   const float* __restrict__ bias,        // [N]
                   float* __restrict__ C,                 // [M, N] fp32
                   int M, int N)
{
    extern __shared__ char dyn[];     // 2 x (16KB A + 16KB B)
    const int tid  = threadIdx.x;
    const int wid  = tid >> 5;
    const int lane = tid & 31;
    const int warp_m = wid & 1;       // 0..1
    const int warp_n = wid >> 1;      // 0..3
    const int row0 = blockIdx.y * 128;
    const int n0   = blockIdx.x * 128;

    const uint32_t sbase = smem_u32(dyn);

    float acc[4][4][4];
#pragma unroll
    for (int i = 0; i < 4; i++)
#pragma unroll
        for (int j = 0; j < 4; j++)
#pragma unroll
            for (int k = 0; k < 4; k++) acc[i][j][k] = 0.f;

    // per-thread load indices (16B granules): idx = tid + i*256 -> r, c
    const uint4* baseA4 = (const uint4*)(A + (size_t)row0 * 512);
    const uint4* baseB4 = (const uint4*)(Bm + (size_t)n0 * 512);

    uint4 va[4], vb[4];

    auto ldg_chunk = [&](int cc) {
        const int seg  = cc >> 2;
        const int kk   = (cc & 3) * 64;
        const int aoff = (seg == 1) ? 256 : 0;
        const int boff = (seg == 2) ? 256 : 0;
        const uint4* sA = baseA4 + ((aoff + kk) >> 3);
        const uint4* sB = baseB4 + ((boff + kk) >> 3);
#pragma unroll
        for (int i = 0; i < 4; i++) {
            const int idx = tid + i * 256;
            const int r = idx >> 3, c = idx & 7;
            va[i] = __ldg(sA + (size_t)r * 64 + c);
            vb[i] = __ldg(sB + (size_t)r * 64 + c);
        }
    };
    auto sts_chunk = [&](int b) {
        char* smA = dyn + b * 32768;
        char* smB = smA + 16384;
#pragma unroll
        for (int i = 0; i < 4; i++) {
            const int idx = tid + i * 256;
            const int r = idx >> 3, c = idx & 7;
            const uint32_t off = r * 128 + c * 16;
            const uint32_t sw  = off ^ ((off >> 3) & 0x70);
            *(uint4*)(smA + sw) = va[i];
            *(uint4*)(smB + sw) = vb[i];
        }
    };

    // ldmatrix per-lane constants: tile t = lane>>3 within .x4
    const int t  = lane >> 3;
    const int l7 = lane & 7;
    const uint32_t tlo = (t & 1) * 8;       // +8 rows for odd tiles
    const uint32_t tc  = (uint32_t)(t >> 1);  // chunk select (k-halves)
    const uint32_t aRowBase = (warp_m * 64 + tlo + l7) * 128;
    const uint32_t bRowBase = (warp_n * 32 + tlo + l7) * 128;

    auto mma_chunk = [&](int b) {
        const uint32_t baseA = sbase + b * 32768;
        const uint32_t baseB = baseA + 16384;
#pragma unroll
        for (int ks = 0; ks < 4; ks++) {
            const uint32_t csw = (uint32_t)(((ks * 2 + tc) ^ l7) << 4);
            uint32_t bf[2][4];
#pragma unroll
            for (int nt = 0; nt < 2; nt++)
                ldsm4(bf[nt], baseB + bRowBase + nt * (16 * 128) + csw);
#pragma unroll
            for (int mt = 0; mt < 4; mt++) {
                uint32_t af[4];
                ldsm4(af, baseA + aRowBase + mt * (16 * 128) + csw);
                mma16816(acc[mt][0], af, bf[0][0], bf[0][2]);
                mma16816(acc[mt][1], af, bf[0][1], bf[0][3]);
                mma16816(acc[mt][2], af, bf[1][0], bf[1][2]);
                mma16816(acc[mt][3], af, bf[1][1], bf[1][3]);
            }
        }
    };

    // pipeline: prologue fill buf0, then LDG(cc+1) | mma(cc) | STS(cc+1)
    ldg_chunk(0);
    sts_chunk(0);
    for (int cc = 0; cc < 12; cc++) {
        if (cc < 11) ldg_chunk(cc + 1);
        __syncthreads();
        mma_chunk(cc & 1);
        if (cc < 11) sts_chunk((cc + 1) & 1);
    }

    // epilogue: fragment -> global with bias
#pragma unroll
    for (int mt = 0; mt < 4; mt++) {
        const int m = row0 + warp_m * 64 + mt * 16 + (lane >> 2);
#pragma unroll
        for (int n8 = 0; n8 < 4; n8++) {
            const int c = n0 + warp_n * 32 + n8 * 8 + (lane & 3) * 2;
            const float bx = __ldg(&bias[c]);
            const float by = __ldg(&bias[c + 1]);
            if (m < M) {
                float2 o = make_float2(acc[mt][n8][0] + bx, acc[mt][n8][1] + by);
                *(float2*)(C + (size_t)m * N + c) = o;
            }
            if (m + 8 < M) {
                float2 o = make_float2(acc[mt][n8][2] + bx, acc[mt][n8][3] + by);
                *(float2*)(C + (size_t)(m + 8) * N + c) = o;
            }
        }
    }
}

// ---------------------------------------------------------------------------
// Deformable sampling; writes bf16 hi/lo directly into A_cat of final GEMM.
// ---------------------------------------------------------------------------
__global__ __launch_bounds__(256)
void msda_sample(const float* __restrict__ refp,   // [B, LQ, 4, 2]
                 const float* __restrict__ proj,   // [M, 384]
                 const float* __restrict__ value,  // [B, LEN_IN, 8, 32]
                 __nv_bfloat16* __restrict__ acat) // [M_PAD, 512]
{
    __shared__ float4 sW[128];
    __shared__ int4   sO[128];

    const int bq = blockIdx.x;
    const int tt = threadIdx.x;
    const int b  = bq / LQ_;

    if (tt < 128) {
        const int hd  = tt >> 4;
        const int p   = tt & 15;
        const int lvl = p >> 2;
        const int pp  = p & 3;

        float a = proj[bq * 384 + 256 + hd * 16 + p];
        float m = a;
#pragma unroll
        for (int o = 8; o; o >>= 1) m = fmaxf(m, __shfl_xor_sync(FULL, m, o));
        float e = __expf(a - m);
        float s = e;
#pragma unroll
        for (int o = 8; o; o >>= 1) s += __shfl_xor_sync(FULL, s, o);
        const float w = e / s;

        const float wh = c_WH[lvl];
        const int   Wl = c_Wi[lvl];
        const int   Sl = c_S[lvl];
        const float ox = proj[bq * 384 + hd * 32 + lvl * 8 + pp * 2 + 0];
        const float oy = proj[bq * 384 + hd * 32 + lvl * 8 + pp * 2 + 1];
        const float rx = refp[(bq * 4 + lvl) * 2 + 0];
        const float ry = refp[(bq * 4 + lvl) * 2 + 1];

        const float x = fmaf(rx, wh, ox) - 0.5f;
        const float y = fmaf(ry, wh, oy) - 0.5f;

        const float fx0 = floorf(x), fy0 = floorf(y);
        const int   x0  = (int)fx0,  y0  = (int)fy0;
        const float tx_ = x - fx0,   ty_ = y - fy0;

        const bool vx0 = (x0 >= 0)     && (x0 < Wl);
        const bool vx1 = (x0 + 1 >= 0) && (x0 + 1 < Wl);
        const bool vy0 = (y0 >= 0)     && (y0 < Wl);
        const bool vy1 = (y0 + 1 >= 0) && (y0 + 1 < Wl);

        const int cx0 = min(max(x0, 0),     Wl - 1);
        const int cx1 = min(max(x0 + 1, 0), Wl - 1);
        const int cy0 = min(max(y0, 0),     Wl - 1);
        const int cy1 = min(max(y0 + 1, 0), Wl - 1);

        float4 wv;
        wv.x = (vx0 && vy0) ? (1.f - tx_) * (1.f - ty_) * w : 0.f;
        wv.y = (vx1 && vy0) ? tx_ * (1.f - ty_) * w : 0.f;
        wv.z = (vx0 && vy1) ? (1.f - tx_) * ty_ * w : 0.f;
        wv.w = (vx1 && vy1) ? tx_ * ty_ * w : 0.f;

        const int base = b * LEN_IN_ * DM_ + hd * 32;
        int4 ov;
        ov.x = base + (Sl + cy0 * Wl + cx0) * DM_;
        ov.y = base + (Sl + cy0 * Wl + cx1) * DM_;
        ov.z = base + (Sl + cy1 * Wl + cx0) * DM_;
        ov.w = base + (Sl + cy1 * Wl + cx1) * DM_;

        sW[tt] = wv;
        sO[tt] = ov;
    }
    __syncthreads();

    const int hd   = tt >> 5;
    const int lane = tt & 31;
    const float* __restrict__ vp = value + lane;

    float acc = 0.f;
#pragma unroll
    for (int p = 0; p < 16; p++) {
        const float4 wv = sW[hd * 16 + p];
        const int4   ov = sO[hd * 16 + p];
        acc = fmaf(wv.x, __ldg(vp + ov.x), acc);
        acc = fmaf(wv.y, __ldg(vp + ov.y), acc);
        acc = fmaf(wv.z, __ldg(vp + ov.z), acc);
        acc = fmaf(wv.w, __ldg(vp + ov.w), acc);
    }

    __nv_bfloat16 h, l; split_bf16(acc, h, l);
    acat[(size_t)bq * 512 + hd * 32 + lane]       = h;
    acat[(size_t)bq * 512 + 256 + hd * 32 + lane] = l;
}

// ---------------------------------------------------------------------------
extern "C" void kernel_launch(void* const* d_in, const int* in_sizes, int n_in,
                              void* d_out, int out_size)
{
    const float* query  = (const float*)d_in[0];
    const float* refp   = (const float*)d_in[1];
    const float* inflat = (const float*)d_in[2];
    const float* W_off  = (const float*)d_in[5];
    const float* b_off  = (const float*)d_in[6];
    const float* W_attn = (const float*)d_in[7];
    const float* b_attn = (const float*)d_in[8];
    const float* W_val  = (const float*)d_in[9];
    const float* b_val  = (const float*)d_in[10];
    const float* W_out  = (const float*)d_in[11];
    const float* b_out  = (const float*)d_in[12];
    float* out = (float*)d_out;

    void *pA1, *pA2, *pA3, *pBval, *pBqkv, *pBout, *pbcat, *pvalue, *pproj;
    cudaGetSymbolAddress(&pA1, g_Acat1);
    cudaGetSymbolAddress(&pA2, g_Acat2);
    cudaGetSymbolAddress(&pA3, g_Acat3);
    cudaGetSymbolAddress(&pBval, g_Bval);
    cudaGetSymbolAddress(&pBqkv, g_Bqkv);
    cudaGetSymbolAddress(&pBout, g_Bout);
    cudaGetSymbolAddress(&pbcat, g_bcat);
    cudaGetSymbolAddress(&pvalue, g_value);
    cudaGetSymbolAddress(&pproj, g_proj);

    const int DSMEM = 2 * 32768;   // 64KB
    cudaFuncSetAttribute(gemm_bf16_mma,
                         cudaFuncAttributeMaxDynamicSharedMemorySize, DSMEM);

    pack_misc<<<dim3(768, 4), 256>>>(W_off, b_off, W_attn, b_attn, W_val, W_out);

    convert_split<<<dim3((M_ROWS * 64 + 255) / 256, 2), 256>>>(inflat, query);

    gemm_bf16_mma<<<dim3(2, MT_), 256, DSMEM>>>(
        (const __nv_bfloat16*)pA1, (const __nv_bfloat16*)pBval,
        b_val, (float*)pvalue, M_ROWS, 256);

    gemm_bf16_mma<<<dim3(3, MT_), 256, DSMEM>>>(
        (const __nv_bfloat16*)pA2, (const __nv_bfloat16*)pBqkv,
        (const float*)pbcat, (float*)pproj, M_ROWS, 384);

    msda_sample<<<M_ROWS, 256>>>(refp, (const float*)pproj,
                                 (const float*)pvalue, (__nv_bfloat16*)pA3);

    gemm_bf16_mma<<<dim3(2, MT_), 256, DSMEM>>>(
        (const __nv_bfloat16*)pA3, (const __nv_bfloat16*)pBout,
        b_out, out, M_ROWS, 256);
}

// round 9
// speedup vs baseline: 2.1531x; 1.1507x over previous
#include <cuda_runtime.h>
#include <cuda_bf16.h>
#include <math.h>
#include <stdint.h>

#define FULL 0xFFFFFFFFu

static constexpr int B_      = 2;
static constexpr int LQ_     = 13294;
static constexpr int LEN_IN_ = 13294;
static constexpr int DM_     = 256;
static constexpr int M_ROWS  = B_ * LQ_;      // 26588
static constexpr int MT_     = 208;           // M tiles of 128
static constexpr int M_PAD   = MT_ * 128;     // 26624

// ---------------- scratch (static device globals; allocation-free) ----------
__device__ __align__(128) __nv_bfloat16 g_Acat1[M_PAD * 512];  // bf16(inflat) hi|lo
__device__ __align__(128) __nv_bfloat16 g_Acat2[M_PAD * 512];  // bf16(query)  hi|lo
__device__ __align__(128) __nv_bfloat16 g_Acat3[M_PAD * 512];  // bf16(sampled) hi|lo
__device__ __align__(128) __nv_bfloat16 g_Bval[256 * 512];     // B[n,k] hi|lo
__device__ __align__(128) __nv_bfloat16 g_Bqkv[384 * 512];
__device__ __align__(128) __nv_bfloat16 g_Bout[256 * 512];
__device__ float g_bcat[384];
__device__ float g_value[M_ROWS * 256];       // fp32 value (sampler input)
__device__ float g_proj [M_ROWS * 384];       // fp32 [off(256) | logits(128)]

__constant__ float c_WH[4] = {100.f, 50.f, 25.f, 13.f};
__constant__ int   c_Wi[4] = {100, 50, 25, 13};
__constant__ int   c_S [4] = {0, 10000, 12500, 13125};

// ---------------- helpers ---------------------------------------------------
__device__ __forceinline__ void split_bf16(float x, __nv_bfloat16& h, __nv_bfloat16& l) {
    h = __float2bfloat16(x);
    l = __float2bfloat16(x - __bfloat162float(h));
}
__device__ __forceinline__ uint32_t smem_u32(const void* p) {
    uint32_t a;
    asm("{ .reg .u64 t; cvta.to.shared.u64 t, %1; cvt.u32.u64 %0, t; }" : "=r"(a) : "l"(p));
    return a;
}
__device__ __forceinline__ void ldsm4(uint32_t* r, uint32_t a) {
    asm volatile("ldmatrix.sync.aligned.m8n8.x4.shared.b16 {%0,%1,%2,%3}, [%4];"
                 : "=r"(r[0]), "=r"(r[1]), "=r"(r[2]), "=r"(r[3]) : "r"(a));
}
__device__ __forceinline__ void mma16816(float* d, const uint32_t* a,
                                         uint32_t b0, uint32_t b1) {
    asm volatile(
        "mma.sync.aligned.m16n8k16.row.col.f32.bf16.bf16.f32 "
        "{%0,%1,%2,%3}, {%4,%5,%6,%7}, {%8,%9}, {%0,%1,%2,%3};"
        : "+f"(d[0]), "+f"(d[1]), "+f"(d[2]), "+f"(d[3])
        : "r"(a[0]), "r"(a[1]), "r"(a[2]), "r"(a[3]), "r"(b0), "r"(b1));
}
__device__ __forceinline__ void cp16(uint32_t dst, const void* src) {
    asm volatile("cp.async.cg.shared.global [%0], [%1], 16;" :: "r"(dst), "l"(src));
}
__device__ __forceinline__ void cp_commit() {
    asm volatile("cp.async.commit_group;" ::: "memory");
}
template<int N> __device__ __forceinline__ void cp_wait() {
    asm volatile("cp.async.wait_group %0;" :: "n"(N) : "memory");
}

// ---------------------------------------------------------------------------
// Pack weights: B[n, 0:256]=bf16_hi(W[k,n]), B[n, 256:512]=bf16_lo. Plus the
// concatenated bias and zero-fill of the A_cat pad rows.
// ---------------------------------------------------------------------------
__global__ void pack_misc(const float* __restrict__ Woff,  const float* __restrict__ boff,
                          const float* __restrict__ Wattn, const float* __restrict__ battn,
                          const float* __restrict__ Wval,  const float* __restrict__ Wout)
{
    const int i = blockIdx.x * blockDim.x + threadIdx.x;
    const int which = blockIdx.y;
    if (which == 0) {
        if (i < 256 * 512) {
            int n = i >> 9, kk = i & 511, k = kk & 255;
            float w = Wval[k * 256 + n];
            __nv_bfloat16 h, l; split_bf16(w, h, l);
            g_Bval[i] = (kk < 256) ? h : l;
        }
    } else if (which == 1) {
        if (i < 384 * 512) {
            int n = i >> 9, kk = i & 511, k = kk & 255;
            float w = (n < 256) ? Woff[k * 256 + n] : Wattn[k * 128 + (n - 256)];
            __nv_bfloat16 h, l; split_bf16(w, h, l);
            g_Bqkv[i] = (kk < 256) ? h : l;
        }
    } else if (which == 2) {
        if (i < 256 * 512) {
            int n = i >> 9, kk = i & 511, k = kk & 255;
            float w = Wout[k * 256 + n];
            __nv_bfloat16 h, l; split_bf16(w, h, l);
            g_Bout[i] = (kk < 256) ? h : l;
        }
    } else {
        if (i < 384) g_bcat[i] = (i < 256) ? boff[i] : battn[i - 256];
        int j = i - 384;
        const int PADE = (M_PAD - M_ROWS) * 512;   // 36*512
        if (j >= 0 && j < 3 * PADE) {
            int arr = j / PADE, off = j % PADE;
            __nv_bfloat16 z = __float2bfloat16(0.f);
            __nv_bfloat16* dst = (arr == 0) ? g_Acat1 : (arr == 1) ? g_Acat2 : g_Acat3;
            dst[M_ROWS * 512 + off] = z;
        }
    }
}

// ---------------------------------------------------------------------------
// fp32 [M,256] -> bf16 split [M,512] for inflat (y=0) and query (y=1).
// ---------------------------------------------------------------------------
__global__ void convert_split(const float* __restrict__ inflat,
                              const float* __restrict__ query)
{
    const int e4 = blockIdx.x * blockDim.x + threadIdx.x;
    if (e4 >= M_ROWS * 64) return;
    const float* src = blockIdx.y ? query : inflat;
    __nv_bfloat16* dst = blockIdx.y ? g_Acat2 : g_Acat1;
    const int row = e4 >> 6;
    const int c4  = (e4 & 63) << 2;
    float4 v = *(const float4*)(src + (size_t)row * 256 + c4);
    __nv_bfloat16 h0, l0, h1, l1, h2, l2, h3, l3;
    split_bf16(v.x, h0, l0); split_bf16(v.y, h1, l1);
    split_bf16(v.z, h2, l2); split_bf16(v.w, h3, l3);
    __nv_bfloat162* dh = (__nv_bfloat162*)(dst + (size_t)row * 512 + c4);
    dh[0] = __halves2bfloat162(h0, h1);
    dh[1] = __halves2bfloat162(h2, h3);
    __nv_bfloat162* dl = (__nv_bfloat162*)(dst + (size_t)row * 512 + 256 + c4);
    dl[0] = __halves2bfloat162(l0, l1);
    dl[1] = __halves2bfloat162(l2, l3);
}

// ---------------------------------------------------------------------------
// bf16 split GEMM via mma.sync + cp.async 3-stage pipeline. One CTA = 128x128
// tile, 256 threads = 8 warps (2x4), warp tile 64x32. 12 K-chunks of 64
// (3 segments: Ahi*Bhi, Alo*Bhi, Ahi*Blo), fp32 acc. 2 CTAs/SM.
// Dual-problem: blocks with blockIdx.x >= split switch to the second set.
// ---------------------------------------------------------------------------
__global__ __launch_bounds__(256, 2)
void gemm_bf16_mma(const __nv_bfloat16* __restrict__ A,
                   const __nv_bfloat16* __restrict__ Bm,
                   const float* __restrict__ bias,
                   float* __restrict__ C, int M, int N, int split,
                   const __nv_bfloat16* __restrict__ A2,
                   const __nv_bfloat16* __restrict__ B2,
                   const float* __restrict__ bias2,
                   float* __restrict__ C2, int N2)
{
    extern __shared__ char dyn[];     // 3 x (16KB A + 16KB B)
    const int tid  = threadIdx.x;
    const int wid  = tid >> 5;
    const int lane = tid & 31;
    const int warp_m = wid & 1;
    const int warp_n = wid >> 1;

    int bx = blockIdx.x;
    if (bx >= split) { A = A2; Bm = B2; bias = bias2; C = C2; N = N2; bx -= split; }
    const int row0 = blockIdx.y * 128;
    const int n0   = bx * 128;

    const uint32_t sbase = smem_u32(dyn);

    float acc[4][4][4];
#pragma unroll
    for (int i = 0; i < 4; i++)
#pragma unroll
        for (int j = 0; j < 4; j++)
#pragma unroll
            for (int k = 0; k < 4; k++) acc[i][j][k] = 0.f;

    const uint4* baseA4 = (const uint4*)(A + (size_t)row0 * 512);
    const uint4* baseB4 = (const uint4*)(Bm + (size_t)n0 * 512);

    // per-thread copy geometry: thread -> row cr (0..31 step +32), 16B col ccol
    const int cr = tid >> 3, ccol = tid & 7;

    auto issue_chunk = [&](int cc) {
        const int s    = cc - (cc / 3) * 3;   // cc % 3
        const int seg  = cc >> 2;
        const int kk   = (cc & 3) * 64;
        const int aoff = (seg == 1) ? 256 : 0;
        const int boff = (seg == 2) ? 256 : 0;
        const uint4* sA = baseA4 + ((aoff + kk) >> 3);
        const uint4* sB = baseB4 + ((boff + kk) >> 3);
        const uint32_t smA = sbase + s * 32768;
        const uint32_t smB = smA + 16384;
#pragma unroll
        for (int i = 0; i < 4; i++) {
            const int r = cr + i * 32;
            const uint32_t off = r * 128 + ccol * 16;
            const uint32_t sw  = off ^ ((off >> 3) & 0x70);
            cp16(smA + sw, sA + (size_t)r * 64 + ccol);
            cp16(smB + sw, sB + (size_t)r * 64 + ccol);
        }
        cp_commit();
    };

    // ldmatrix per-lane constants
    const int t  = lane >> 3;
    const int l7 = lane & 7;
    const uint32_t tlo = (t & 1) * 8;
    const uint32_t tc  = (uint32_t)(t >> 1);
    const uint32_t aRowBase = (warp_m * 64 + tlo + l7) * 128;
    const uint32_t bRowBase = (warp_n * 32 + tlo + l7) * 128;

    auto mma_chunk = [&](int s) {
        const uint32_t baseA = sbase + s * 32768;
        const uint32_t baseB = baseA + 16384;
#pragma unroll
        for (int ks = 0; ks < 4; ks++) {
            const uint32_t csw = (uint32_t)(((ks * 2 + tc) ^ l7) << 4);
            uint32_t bf[2][4];
#pragma unroll
            for (int nt = 0; nt < 2; nt++)
                ldsm4(bf[nt], baseB + bRowBase + nt * (16 * 128) + csw);
#pragma unroll
            for (int mt = 0; mt < 4; mt++) {
                uint32_t af[4];
                ldsm4(af, baseA + aRowBase + mt * (16 * 128) + csw);
                mma16816(acc[mt][0], af, bf[0][0], bf[0][2]);
                mma16816(acc[mt][1], af, bf[0][1], bf[0][3]);
                mma16816(acc[mt][2], af, bf[1][0], bf[1][2]);
                mma16816(acc[mt][3], af, bf[1][1], bf[1][3]);
            }
        }
    };

    // 3-stage pipeline over 12 chunks
    issue_chunk(0);
    issue_chunk(1);
    int sidx = 0;
    for (int cc = 0; cc < 12; cc++) {
        if (cc < 11) cp_wait<1>(); else cp_wait<0>();
        __syncthreads();
        mma_chunk(sidx);
        __syncthreads();
        if (cc + 2 < 12) issue_chunk(cc + 2);
        sidx = (sidx == 2) ? 0 : sidx + 1;
    }

    // epilogue: fragment -> global with bias
#pragma unroll
    for (int mt = 0; mt < 4; mt++) {
        const int m = row0 + warp_m * 64 + mt * 16 + (lane >> 2);
#pragma unroll
        for (int n8 = 0; n8 < 4; n8++) {
            const int c = n0 + warp_n * 32 + n8 * 8 + (lane & 3) * 2;
            const float bx2 = __ldg(&bias[c]);
            const float by2 = __ldg(&bias[c + 1]);
            if (m < M) {
                float2 o = make_float2(acc[mt][n8][0] + bx2, acc[mt][n8][1] + by2);
                *(float2*)(C + (size_t)m * N + c) = o;
            }
            if (m + 8 < M) {
                float2 o = make_float2(acc[mt][n8][2] + bx2, acc[mt][n8][3] + by2);
                *(float2*)(C + (size_t)(m + 8) * N + c) = o;
            }
        }
    }
}

// ---------------------------------------------------------------------------
// Deformable sampling; writes bf16 hi/lo directly into A_cat of final GEMM.
// ---------------------------------------------------------------------------
__global__ __launch_bounds__(256)
void msda_sample(const float* __restrict__ refp,   // [B, LQ, 4, 2]
                 const float* __restrict__ proj,   // [M, 384]
                 const float* __restrict__ value,  // [B, LEN_IN, 8, 32]
                 __nv_bfloat16* __restrict__ acat) // [M_PAD, 512]
{
    __shared__ float4 sW[128];
    __shared__ int4   sO[128];

    const int bq = blockIdx.x;
    const int tt = threadIdx.x;
    const int b  = bq / LQ_;

    if (tt < 128) {
        const int hd  = tt >> 4;
        const int p   = tt & 15;
        const int lvl = p >> 2;
        const int pp  = p & 3;

        float a = proj[bq * 384 + 256 + hd * 16 + p];
        float m = a;
#pragma unroll
        for (int o = 8; o; o >>= 1) m = fmaxf(m, __shfl_xor_sync(FULL, m, o));
        float e = __expf(a - m);
        float s = e;
#pragma unroll
        for (int o = 8; o; o >>= 1) s += __shfl_xor_sync(FULL, s, o);
        const float w = e / s;

        const float wh = c_WH[lvl];
        const int   Wl = c_Wi[lvl];
        const int   Sl = c_S[lvl];
        const float ox = proj[bq * 384 + hd * 32 + lvl * 8 + pp * 2 + 0];
        const float oy = proj[bq * 384 + hd * 32 + lvl * 8 + pp * 2 + 1];
        const float rx = refp[(bq * 4 + lvl) * 2 + 0];
        const float ry = refp[(bq * 4 + lvl) * 2 + 1];

        const float x = fmaf(rx, wh, ox) - 0.5f;
        const float y = fmaf(ry, wh, oy) - 0.5f;

        const float fx0 = floorf(x), fy0 = floorf(y);
        const int   x0  = (int)fx0,  y0  = (int)fy0;
        const float tx_ = x - fx0,   ty_ = y - fy0;

        const bool vx0 = (x0 >= 0)     && (x0 < Wl);
        const bool vx1 = (x0 + 1 >= 0) && (x0 + 1 < Wl);
        const bool vy0 = (y0 >= 0)     && (y0 < Wl);
        const bool vy1 = (y0 + 1 >= 0) && (y0 + 1 < Wl);

        const int cx0 = min(max(x0, 0),     Wl - 1);
        const int cx1 = min(max(x0 + 1, 0), Wl - 1);
        const int cy0 = min(max(y0, 0),     Wl - 1);
        const int cy1 = min(max(y0 + 1, 0), Wl - 1);

        float4 wv;
        wv.x = (vx0 && vy0) ? (1.f - tx_) * (1.f - ty_) * w : 0.f;
        wv.y = (vx1 && vy0) ? tx_ * (1.f - ty_) * w : 0.f;
        wv.z = (vx0 && vy1) ? (1.f - tx_) * ty_ * w : 0.f;
        wv.w = (vx1 && vy1) ? tx_ * ty_ * w : 0.f;

        const int base = b * LEN_IN_ * DM_ + hd * 32;
        int4 ov;
        ov.x = base + (Sl + cy0 * Wl + cx0) * DM_;
        ov.y = base + (Sl + cy0 * Wl + cx1) * DM_;
        ov.z = base + (Sl + cy1 * Wl + cx0) * DM_;
        ov.w = base + (Sl + cy1 * Wl + cx1) * DM_;

        sW[tt] = wv;
        sO[tt] = ov;
    }
    __syncthreads();

    const int hd   = tt >> 5;
    const int lane = tt & 31;
    const float* __restrict__ vp = value + lane;

    float acc = 0.f;
#pragma unroll
    for (int p = 0; p < 16; p++) {
        const float4 wv = sW[hd * 16 + p];
        const int4   ov = sO[hd * 16 + p];
        acc = fmaf(wv.x, __ldg(vp + ov.x), acc);
        acc = fmaf(wv.y, __ldg(vp + ov.y), acc);
        acc = fmaf(wv.z, __ldg(vp + ov.z), acc);
        acc = fmaf(wv.w, __ldg(vp + ov.w), acc);
    }

    __nv_bfloat16 h, l; split_bf16(acc, h, l);
    acat[(size_t)bq * 512 + hd * 32 + lane]       = h;
    acat[(size_t)bq * 512 + 256 + hd * 32 + lane] = l;
}

// ---------------------------------------------------------------------------
extern "C" void kernel_launch(void* const* d_in, const int* in_sizes, int n_in,
                              void* d_out, int out_size)
{
    const float* query  = (const float*)d_in[0];
    const float* refp   = (const float*)d_in[1];
    const float* inflat = (const float*)d_in[2];
    const float* W_off  = (const float*)d_in[5];
    const float* b_off  = (const float*)d_in[6];
    const float* W_attn = (const float*)d_in[7];
    const float* b_attn = (const float*)d_in[8];
    const float* W_val  = (const float*)d_in[9];
    const float* b_val  = (const float*)d_in[10];
    const float* W_out  = (const float*)d_in[11];
    const float* b_out  = (const float*)d_in[12];
    float* out = (float*)d_out;

    void *pA1, *pA2, *pA3, *pBval, *pBqkv, *pBout, *pbcat, *pvalue, *pproj;
    cudaGetSymbolAddress(&pA1, g_Acat1);
    cudaGetSymbolAddress(&pA2, g_Acat2);
    cudaGetSymbolAddress(&pA3, g_Acat3);
    cudaGetSymbolAddress(&pBval, g_Bval);
    cudaGetSymbolAddress(&pBqkv, g_Bqkv);
    cudaGetSymbolAddress(&pBout, g_Bout);
    cudaGetSymbolAddress(&pbcat, g_bcat);
    cudaGetSymbolAddress(&pvalue, g_value);
    cudaGetSymbolAddress(&pproj, g_proj);

    const int DSMEM = 3 * 32768;   // 96KB
    cudaFuncSetAttribute(gemm_bf16_mma,
                         cudaFuncAttributeMaxDynamicSharedMemorySize, DSMEM);

    pack_misc<<<dim3(768, 4), 256>>>(W_off, b_off, W_attn, b_attn, W_val, W_out);

    convert_split<<<dim3((M_ROWS * 64 + 255) / 256, 2), 256>>>(inflat, query);

    // fused launch: blocks x<2 -> value GEMM (A1*Bval), x>=2 -> proj GEMM (A2*Bqkv)
    gemm_bf16_mma<<<dim3(5, MT_), 256, DSMEM>>>(
        (const __nv_bfloat16*)pA1, (const __nv_bfloat16*)pBval,
        b_val, (float*)pvalue, M_ROWS, 256, 2,
        (const __nv_bfloat16*)pA2, (const __nv_bfloat16*)pBqkv,
        (const float*)pbcat, (float*)pproj, 384);

    msda_sample<<<M_ROWS, 256>>>(refp, (const float*)pproj,
                                 (const float*)pvalue, (__nv_bfloat16*)pA3);

    gemm_bf16_mma<<<dim3(2, MT_), 256, DSMEM>>>(
        (const __nv_bfloat16*)pA3, (const __nv_bfloat16*)pBout,
        b_out, out, M_ROWS, 256, 2,
        (const __nv_bfloat16*)pA3, (const __nv_bfloat16*)pBout,
        b_out, out, 256);
}